// round 2
// baseline (speedup 1.0000x reference)
#include <cuda_runtime.h>
#include <math.h>

#define S_LEN 2048
#define B_SZ  64
#define D     512      // D_IN = D_SRC = D_ALIGN
#define KCAT  1024

// ---------------- scratch (no allocs allowed) ----------------
__device__ float g_xa[B_SZ * D];          // x @ W1a^T + b1   [b][a]
__device__ float g_scores[S_LEN * B_SZ];  // pre-softmax scores [s][b]

// ---------------- K0: zero scores + ctx out ----------------
__global__ void k_zero(float* __restrict__ ctx) {
    int i = blockIdx.x * 256 + threadIdx.x;   // grid covers 131072 exactly
    g_scores[i] = 0.0f;
    if (i < B_SZ * D) ctx[i] = 0.0f;
}

// ---------------- K1: xa[b][a] = dot(x[b,:], W1[a,0:512]) + b1[a] ----------------
// one warp per output element; lanes stride over K=512.
__global__ void k_xa(const float* __restrict__ x, const float* __restrict__ W1,
                     const float* __restrict__ b1) {
    int w    = (blockIdx.x * blockDim.x + threadIdx.x) >> 5;  // 0..32767
    int lane = threadIdx.x & 31;
    int b = w >> 9;        // / 512
    int a = w & 511;
    const float* xr = x  + b * D;
    const float* wr = W1 + (size_t)a * KCAT;   // first 512 cols = x part
    float sum = 0.0f;
    #pragma unroll
    for (int i = 0; i < 16; i++) {
        int d = lane + i * 32;
        sum = fmaf(xr[d], wr[d], sum);
    }
    #pragma unroll
    for (int o = 16; o; o >>= 1) sum += __shfl_xor_sync(0xffffffffu, sum, o);
    if (lane == 0) g_xa[b * D + a] = sum + b1[a];
}

// ---------------- K2: fused GEMM + tanh + w2 dot -> scores ----------------
// scores[s*64+b] = sum_a tanh( xa[b][a] + sum_d src[s][b][d]*W1[a][512+d] ) * w2[a]
// Tile: BM=128 rows (r = s*64+b), BN=128 (a), BK=16. 256 threads, 8x8 microtile.
#define BM 128
#define BN 128
#define BK 16

__global__ __launch_bounds__(256, 2) void k_gemm_scores(
    const float* __restrict__ src,   // [S*B][512]
    const float* __restrict__ W1,    // [512][1024]
    const float* __restrict__ w2)    // [512]
{
    __shared__ float As[BM][BK + 1];
    __shared__ float Bs[BN][BK + 1];

    const int m0  = blockIdx.y * BM;     // global row base
    const int n0  = blockIdx.x * BN;     // a base
    const int tid = threadIdx.x;
    const int tx  = tid & 15;            // col group
    const int ty  = tid >> 4;            // row group

    float acc[8][8];
    #pragma unroll
    for (int i = 0; i < 8; i++)
        #pragma unroll
        for (int j = 0; j < 8; j++) acc[i][j] = 0.0f;

    const float* Bbase = W1 + 512;       // W1b = W1[:, 512:1024]

    for (int k0 = 0; k0 < D; k0 += BK) {
        // load A tile 128x16 as float4 (2 per thread)
        #pragma unroll
        for (int i = 0; i < 2; i++) {
            int e4 = tid + i * 256;          // 0..511
            int r  = e4 >> 2;                // 0..127
            int c4 = e4 & 3;                 // 0..3
            float4 v = *(const float4*)(src + (size_t)(m0 + r) * D + k0 + c4 * 4);
            As[r][c4 * 4 + 0] = v.x;
            As[r][c4 * 4 + 1] = v.y;
            As[r][c4 * 4 + 2] = v.z;
            As[r][c4 * 4 + 3] = v.w;
        }
        // load B tile 128x16 (W1b rows a = n0..n0+127)
        #pragma unroll
        for (int i = 0; i < 2; i++) {
            int e4 = tid + i * 256;
            int r  = e4 >> 2;
            int c4 = e4 & 3;
            float4 v = *(const float4*)(Bbase + (size_t)(n0 + r) * KCAT + k0 + c4 * 4);
            Bs[r][c4 * 4 + 0] = v.x;
            Bs[r][c4 * 4 + 1] = v.y;
            Bs[r][c4 * 4 + 2] = v.z;
            Bs[r][c4 * 4 + 3] = v.w;
        }
        __syncthreads();

        #pragma unroll
        for (int k = 0; k < BK; k++) {
            float af[8], bf[8];
            #pragma unroll
            for (int i = 0; i < 8; i++) af[i] = As[ty * 8 + i][k];
            #pragma unroll
            for (int j = 0; j < 8; j++) bf[j] = Bs[tx * 8 + j][k];
            #pragma unroll
            for (int i = 0; i < 8; i++)
                #pragma unroll
                for (int j = 0; j < 8; j++)
                    acc[i][j] = fmaf(af[i], bf[j], acc[i][j]);
        }
        __syncthreads();
    }

    // epilogue: + xa, tanh, * w2, reduce over a within tile, atomic into scores
    #pragma unroll
    for (int i = 0; i < 8; i++) {
        int R = m0 + ty * 8 + i;           // global row = s*64 + b
        int b = R & 63;
        float part = 0.0f;
        #pragma unroll
        for (int j = 0; j < 8; j++) {
            int a  = n0 + tx * 8 + j;
            float h = tanhf(acc[i][j] + g_xa[b * D + a]);
            part = fmaf(h, __ldg(&w2[a]), part);
        }
        // reduce across the 16 tx lanes (contiguous within half-warp)
        #pragma unroll
        for (int o = 8; o; o >>= 1) part += __shfl_xor_sync(0xffffffffu, part, o);
        if (tx == 0) atomicAdd(&g_scores[R], part);
    }
}

// ---------------- K3: softmax over S (per column b) ----------------
__global__ void k_softmax(const unsigned char* __restrict__ mask,
                          float* __restrict__ attn)   // [s][b]
{
    const int b = blockIdx.x;
    const int t = threadIdx.x;     // 256 threads, 8 elems each
    __shared__ float red[256];

    float v[8];
    float mx = -INFINITY;
    #pragma unroll
    for (int i = 0; i < 8; i++) {
        int s = t + i * 256;
        float xv = g_scores[s * B_SZ + b];
        if (mask[s * B_SZ + b]) xv = -INFINITY;
        v[i] = xv;
        mx = fmaxf(mx, xv);
    }
    red[t] = mx; __syncthreads();
    for (int o = 128; o; o >>= 1) {
        if (t < o) red[t] = fmaxf(red[t], red[t + o]);
        __syncthreads();
    }
    mx = red[0]; __syncthreads();

    float sum = 0.0f;
    #pragma unroll
    for (int i = 0; i < 8; i++) {
        v[i] = expf(v[i] - mx);
        sum += v[i];
    }
    red[t] = sum; __syncthreads();
    for (int o = 128; o; o >>= 1) {
        if (t < o) red[t] += red[t + o];
        __syncthreads();
    }
    float inv = 1.0f / red[0];
    #pragma unroll
    for (int i = 0; i < 8; i++)
        attn[(t + i * 256) * B_SZ + b] = v[i] * inv;
}

// ---------------- K4: ctx[b][d] = sum_s attn[s][b] * src[s][b][d] ----------------
__global__ void k_ctx(const float* __restrict__ src,
                      const float* __restrict__ attn,
                      float* __restrict__ ctx)
{
    const int b     = blockIdx.x;
    const int chunk = blockIdx.y;     // 32 chunks of 64 s
    const int d     = threadIdx.x;    // 512
    const int s0    = chunk * 64;
    float acc = 0.0f;
    #pragma unroll 8
    for (int i = 0; i < 64; i++) {
        int s = s0 + i;
        float a = __ldg(&attn[s * B_SZ + b]);
        acc = fmaf(a, src[((size_t)s * B_SZ + b) * D + d], acc);
    }
    atomicAdd(&ctx[b * D + d], acc);
}

// ---------------- launch ----------------
extern "C" void kernel_launch(void* const* d_in, const int* in_sizes, int n_in,
                              void* d_out, int out_size) {
    const float*         x    = (const float*)d_in[0];          // [1,B,512]
    const float*         src  = (const float*)d_in[1];          // [S,B,512]
    const unsigned char* mask = (const unsigned char*)d_in[2];  // [S,B] bool
    const float*         W1   = (const float*)d_in[3];          // [512,1024]
    const float*         b1   = (const float*)d_in[4];          // [512]
    const float*         w2   = (const float*)d_in[5];          // [1,512]
    // d_in[6] = b2: softmax-invariant scalar shift -> not needed

    float* ctx  = (float*)d_out;                 // [B,512]  = 32768
    float* attn = (float*)d_out + B_SZ * D;      // [S,B]    = 131072

    k_zero<<<512, 256>>>(ctx);
    k_xa<<<4096, 256>>>(x, W1, b1);
    {
        dim3 grid(BN == 128 ? 4 : 8, (S_LEN * B_SZ) / BM);   // (4, 1024)
        k_gemm_scores<<<grid, 256>>>(src, W1, w2);
    }
    k_softmax<<<B_SZ, 256>>>(mask, attn);
    {
        dim3 grid(B_SZ, 32);
        k_ctx<<<grid, 512>>>(src, attn, ctx);
    }
}

// round 3
// speedup vs baseline: 3.3153x; 3.3153x over previous
#include <cuda_runtime.h>
#include <math.h>

#define S_LEN 2048
#define B_SZ  64
#define D     512      // D_IN = D_SRC = D_ALIGN
#define KCAT  1024

// ---------------- scratch (no allocs allowed) ----------------
__device__ float g_xa[B_SZ * D];          // x @ W1a^T + b1   [b][a]
__device__ float g_scores[S_LEN * B_SZ];  // pre-softmax scores [s*64+b]

// ---------------- K0: zero scores + ctx out ----------------
__global__ void k_zero(float* __restrict__ ctx) {
    int i = blockIdx.x * 256 + threadIdx.x;   // grid covers 131072 exactly
    g_scores[i] = 0.0f;
    if (i < B_SZ * D) ctx[i] = 0.0f;
}

// ---------------- K1: xa[b][a] = dot(x[b,:], W1[a,0:512]) + b1[a] ----------------
__global__ void k_xa(const float* __restrict__ x, const float* __restrict__ W1,
                     const float* __restrict__ b1) {
    int w    = (blockIdx.x * blockDim.x + threadIdx.x) >> 5;  // 0..32767
    int lane = threadIdx.x & 31;
    int b = w >> 9;        // / 512
    int a = w & 511;
    const float* xr = x  + b * D;
    const float* wr = W1 + (size_t)a * KCAT;   // first 512 cols = x part
    float sum = 0.0f;
    #pragma unroll
    for (int i = 0; i < 16; i++) {
        int d = lane + i * 32;
        sum = fmaf(xr[d], wr[d], sum);
    }
    #pragma unroll
    for (int o = 16; o; o >>= 1) sum += __shfl_xor_sync(0xffffffffu, sum, o);
    if (lane == 0) g_xa[b * D + a] = sum + b1[a];
}

// ---------------- tf32 helpers ----------------
__device__ __forceinline__ unsigned f2tf32(float f) {
    unsigned r;
    asm("cvt.rna.tf32.f32 %0, %1;" : "=r"(r) : "f"(f));
    return r;
}

__device__ __forceinline__ void mma_tf32(float* c, const unsigned* a, const unsigned* b) {
    asm volatile(
        "mma.sync.aligned.m16n8k8.row.col.f32.tf32.tf32.f32 "
        "{%0,%1,%2,%3}, {%4,%5,%6,%7}, {%8,%9}, {%0,%1,%2,%3};"
        : "+f"(c[0]), "+f"(c[1]), "+f"(c[2]), "+f"(c[3])
        : "r"(a[0]), "r"(a[1]), "r"(a[2]), "r"(a[3]), "r"(b[0]), "r"(b[1]));
}

// ---------------- K2: fused tf32 tensor GEMM + tanh + w2 dot -> scores ----------------
// scores[R] += sum_{a in tile} tanh( xa[R&63][a] + sum_d src[R][d]*W1[a][512+d] ) * w2[a]
// BM=128 rows, BN=128 cols, BK=32. 256 threads = 8 warps (4 row x 2 col).
// Warp tile 32x64 = 2 m-atoms x 8 n-atoms of m16n8k8.
#define BM 128
#define BN 128
#define BK 32
#define APAD 36   // row stride in floats: bank = (4*quad + tq) -> conflict-free

__global__ __launch_bounds__(256, 2) void k_gemm_scores(
    const float* __restrict__ src,   // [S*B][512]
    const float* __restrict__ W1,    // [512][1024]
    const float* __restrict__ w2)    // [512]
{
    __shared__ unsigned As[BM * APAD];
    __shared__ unsigned Bs[BN * APAD];

    const int m0   = blockIdx.y * BM;     // global row base (R = s*64+b)
    const int n0   = blockIdx.x * BN;     // a base
    const int tid  = threadIdx.x;
    const int warp = tid >> 5;
    const int lane = tid & 31;
    const int g    = lane >> 2;           // group id (0..7)
    const int tq   = lane & 3;            // thread-in-quad (0..3)
    const int warp_m = warp >> 1;         // 0..3 -> rows warp_m*32
    const int warp_n = warp & 1;          // 0..1 -> cols warp_n*64

    float acc[2][8][4];
    #pragma unroll
    for (int i = 0; i < 2; i++)
        #pragma unroll
        for (int j = 0; j < 8; j++)
            #pragma unroll
            for (int k = 0; k < 4; k++) acc[i][j][k] = 0.0f;

    const float* Bbase = W1 + 512;        // W1b = W1[:, 512:1024]

    for (int k0 = 0; k0 < D; k0 += BK) {
        // load A/B tiles 128x32 fp32 -> tf32 smem. 4 float4 per thread per tile.
        #pragma unroll
        for (int i = 0; i < 4; i++) {
            int id = tid + i * 256;       // 0..1023
            int r  = id >> 3;             // 0..127
            int c4 = id & 7;              // 0..7 (float4 index)
            float4 va = *(const float4*)(src + (size_t)(m0 + r) * D + k0 + c4 * 4);
            unsigned* pa = &As[r * APAD + c4 * 4];
            pa[0] = f2tf32(va.x); pa[1] = f2tf32(va.y);
            pa[2] = f2tf32(va.z); pa[3] = f2tf32(va.w);
            float4 vb = *(const float4*)(Bbase + (size_t)(n0 + r) * KCAT + k0 + c4 * 4);
            unsigned* pb = &Bs[r * APAD + c4 * 4];
            pb[0] = f2tf32(vb.x); pb[1] = f2tf32(vb.y);
            pb[2] = f2tf32(vb.z); pb[3] = f2tf32(vb.w);
        }
        __syncthreads();

        #pragma unroll
        for (int ks = 0; ks < BK / 8; ks++) {
            const int kk = ks * 8;
            // B fragments for all 8 n-atoms
            unsigned bf[8][2];
            #pragma unroll
            for (int na = 0; na < 8; na++) {
                int cb = warp_n * 64 + na * 8 + g;   // a-row within tile
                bf[na][0] = Bs[cb * APAD + kk + tq];
                bf[na][1] = Bs[cb * APAD + kk + tq + 4];
            }
            #pragma unroll
            for (int ma = 0; ma < 2; ma++) {
                int rb = warp_m * 32 + ma * 16;
                unsigned af[4];
                af[0] = As[(rb + g)     * APAD + kk + tq];
                af[1] = As[(rb + g + 8) * APAD + kk + tq];
                af[2] = As[(rb + g)     * APAD + kk + tq + 4];
                af[3] = As[(rb + g + 8) * APAD + kk + tq + 4];
                #pragma unroll
                for (int na = 0; na < 8; na++)
                    mma_tf32(acc[ma][na], af, bf[na]);
            }
        }
        __syncthreads();
    }

    // epilogue: + xa, tanh, * w2, quad-reduce over a, atomic into scores
    #pragma unroll
    for (int ma = 0; ma < 2; ma++) {
        #pragma unroll
        for (int half = 0; half < 2; half++) {
            int R = m0 + warp_m * 32 + ma * 16 + half * 8 + g;
            int b = R & 63;
            const float* xar = g_xa + b * D;
            float part = 0.0f;
            #pragma unroll
            for (int na = 0; na < 8; na++) {
                #pragma unroll
                for (int cp = 0; cp < 2; cp++) {
                    int a = n0 + warp_n * 64 + na * 8 + 2 * tq + cp;
                    float h = tanhf(acc[ma][na][half * 2 + cp] + xar[a]);
                    part = fmaf(h, __ldg(&w2[a]), part);
                }
            }
            part += __shfl_xor_sync(0xffffffffu, part, 1);
            part += __shfl_xor_sync(0xffffffffu, part, 2);
            if (tq == 0) atomicAdd(&g_scores[R], part);
        }
    }
}

// ---------------- K3: softmax over S (per column b) ----------------
__global__ void k_softmax(const unsigned char* __restrict__ mask,
                          float* __restrict__ attn)   // [s][b]
{
    const int b = blockIdx.x;
    const int t = threadIdx.x;     // 256 threads, 8 elems each
    __shared__ float red[256];

    float v[8];
    float mx = -INFINITY;
    #pragma unroll
    for (int i = 0; i < 8; i++) {
        int s = t + i * 256;
        float xv = g_scores[s * B_SZ + b];
        if (mask[s * B_SZ + b]) xv = -INFINITY;
        v[i] = xv;
        mx = fmaxf(mx, xv);
    }
    red[t] = mx; __syncthreads();
    for (int o = 128; o; o >>= 1) {
        if (t < o) red[t] = fmaxf(red[t], red[t + o]);
        __syncthreads();
    }
    mx = red[0]; __syncthreads();

    float sum = 0.0f;
    #pragma unroll
    for (int i = 0; i < 8; i++) {
        v[i] = expf(v[i] - mx);
        sum += v[i];
    }
    red[t] = sum; __syncthreads();
    for (int o = 128; o; o >>= 1) {
        if (t < o) red[t] += red[t + o];
        __syncthreads();
    }
    float inv = 1.0f / red[0];
    #pragma unroll
    for (int i = 0; i < 8; i++)
        attn[(t + i * 256) * B_SZ + b] = v[i] * inv;
}

// ---------------- K4: ctx[b][d] = sum_s attn[s][b] * src[s][b][d] ----------------
__global__ void k_ctx(const float* __restrict__ src,
                      const float* __restrict__ attn,
                      float* __restrict__ ctx)
{
    const int b     = blockIdx.x;
    const int chunk = blockIdx.y;     // 32 chunks of 64 s
    const int d     = threadIdx.x;    // 512
    const int s0    = chunk * 64;
    float acc = 0.0f;
    #pragma unroll 8
    for (int i = 0; i < 64; i++) {
        int s = s0 + i;
        float a = __ldg(&attn[s * B_SZ + b]);
        acc = fmaf(a, src[((size_t)s * B_SZ + b) * D + d], acc);
    }
    atomicAdd(&ctx[b * D + d], acc);
}

// ---------------- launch ----------------
extern "C" void kernel_launch(void* const* d_in, const int* in_sizes, int n_in,
                              void* d_out, int out_size) {
    const float*         x    = (const float*)d_in[0];          // [1,B,512]
    const float*         src  = (const float*)d_in[1];          // [S,B,512]
    const unsigned char* mask = (const unsigned char*)d_in[2];  // [S,B] bool
    const float*         W1   = (const float*)d_in[3];          // [512,1024]
    const float*         b1   = (const float*)d_in[4];          // [512]
    const float*         w2   = (const float*)d_in[5];          // [1,512]
    // d_in[6] = b2: softmax-invariant scalar shift -> not needed

    float* ctx  = (float*)d_out;                 // [B,512]  = 32768
    float* attn = (float*)d_out + B_SZ * D;      // [S,B]    = 131072

    k_zero<<<512, 256>>>(ctx);
    k_xa<<<4096, 256>>>(x, W1, b1);
    {
        dim3 grid(512 / BN, (S_LEN * B_SZ) / BM);   // (4, 1024), x fastest -> A L2 reuse
        k_gemm_scores<<<grid, 256>>>(src, W1, w2);
    }
    k_softmax<<<B_SZ, 256>>>(mask, attn);
    {
        dim3 grid(B_SZ, 32);
        k_ctx<<<grid, 512>>>(src, attn, ctx);
    }
}